// round 2
// baseline (speedup 1.0000x reference)
#include <cuda_runtime.h>

#define NB   4
#define LEN1 32777
#define M1   4097
#define M2   512
#define CH   256

// ------- static scratch (no runtime allocation) -------
__device__ float g_u1[NB * M1 * 1024];   // stage-1 aggregated (pos, c, type)
__device__ float g_u2[NB * M2 * 1024];
__device__ float g_out1[NB * M1 * CH];
__device__ float g_gt2[NB * M2 * CH];
__device__ float g_gt1_0[NB * CH];
__device__ float g_attn[NB * M2 * 32];   // attn (n*4+h) for m<512

// ------------------------------------------------ gt MLP (2 layers, relu)
__global__ void __launch_bounds__(256) gt_kernel(
    const float* __restrict__ gt,
    const float* __restrict__ w1, const float* __restrict__ b1,
    const float* __restrict__ w2, const float* __restrict__ b2)
{
    __shared__ float rs[16][256];
    __shared__ float g1[16][256];
    int tid = threadIdx.x, r0 = blockIdx.x * 16;
    #pragma unroll
    for (int i = 0; i < 16; i++) rs[i][tid] = gt[(size_t)(r0 + i) * CH + tid];
    __syncthreads();
    float acc[16];
    float bias = b1[tid];
    #pragma unroll
    for (int i = 0; i < 16; i++) acc[i] = bias;
    for (int c = 0; c < CH; c++) {
        float w = w1[c * CH + tid];
        #pragma unroll
        for (int i = 0; i < 16; i++) acc[i] = fmaf(rs[i][c], w, acc[i]);
    }
    #pragma unroll
    for (int i = 0; i < 16; i++) g1[i][tid] = fmaxf(acc[i], 0.f);
    __syncthreads();
    bias = b2[tid];
    #pragma unroll
    for (int i = 0; i < 16; i++) acc[i] = bias;
    for (int c = 0; c < CH; c++) {
        float w = w2[c * CH + tid];
        #pragma unroll
        for (int i = 0; i < 16; i++) acc[i] = fmaf(g1[i][c], w, acc[i]);
    }
    #pragma unroll
    for (int i = 0; i < 16; i++) {
        int r = r0 + i;
        g_gt2[(size_t)r * CH + tid] = fmaxf(acc[i], 0.f);
        if ((r & 511) == 0) g_gt1_0[(r >> 9) * CH + tid] = g1[i][tid];
    }
}

// --------------------------------------- attention + node-pair aggregation
template<int STAGE>
__global__ void __launch_bounds__(256) aggregate_kernel(
    const float* __restrict__ xin,
    const float* __restrict__ w_att, const float* __restrict__ b_att)
{
    constexpr int M  = (STAGE == 1) ? M1 : M2;
    constexpr int Lx = (STAGE == 1) ? LEN1 : M1;
    const float* x = (STAGE == 1) ? xin : g_out1;
    float*       u = (STAGE == 1) ? g_u1 : g_u2;

    __shared__ float sp[8][8][4];
    __shared__ float sa[32];

    int c = threadIdx.x, m = blockIdx.x, b = blockIdx.y;
    int lane = c & 31, warp = c >> 5;

    size_t rb = ((size_t)b * Lx + 1 + 8 * (size_t)m) * CH;
    float nd[8];
    #pragma unroll
    for (int j = 0; j < 8; j++) nd[j] = x[rb + (size_t)j * CH + c];
    float src = x[((size_t)b * Lx + m) * CH + c];

    if (STAGE == 1) {
        float4 wa = *(const float4*)&w_att[c * 4];
        #pragma unroll
        for (int n = 0; n < 8; n++) {
            float ft = src + nd[n];
            float p0 = ft * wa.x, p1 = ft * wa.y, p2 = ft * wa.z, p3 = ft * wa.w;
            #pragma unroll
            for (int s = 16; s > 0; s >>= 1) {
                p0 += __shfl_xor_sync(0xffffffff, p0, s);
                p1 += __shfl_xor_sync(0xffffffff, p1, s);
                p2 += __shfl_xor_sync(0xffffffff, p2, s);
                p3 += __shfl_xor_sync(0xffffffff, p3, s);
            }
            if (lane == 0) { sp[warp][n][0]=p0; sp[warp][n][1]=p1; sp[warp][n][2]=p2; sp[warp][n][3]=p3; }
        }
        __syncthreads();
        if (c < 32) {
            int n = c >> 2, h = c & 3;
            float lg = b_att[h];
            #pragma unroll
            for (int w = 0; w < 8; w++) lg += sp[w][n][h];
            float mx = lg;
            #pragma unroll
            for (int msk = 4; msk <= 16; msk <<= 1)
                mx = fmaxf(mx, __shfl_xor_sync(0xffffffff, mx, msk));
            float e = expf(lg - mx);
            float sum = e;
            #pragma unroll
            for (int msk = 4; msk <= 16; msk <<= 1)
                sum += __shfl_xor_sync(0xffffffff, sum, msk);
            float a = e / sum;
            sa[c] = a;
            if (m < M2) g_attn[((size_t)b * M2 + m) * 32 + c] = a;
        }
    } else {
        if (c < 32) sa[c] = g_attn[((size_t)b * M2 + m) * 32 + c];
    }
    __syncthreads();

    int g = c >> 6;
    float4 v;
    v.x = sa[0*4+g]*nd[0] + sa[1*4+g]*nd[1];
    v.y = sa[2*4+g]*nd[2] + sa[3*4+g]*nd[3];
    v.z = sa[4*4+g]*nd[4] + sa[5*4+g]*nd[5];
    v.w = sa[6*4+g]*nd[6] + sa[7*4+g]*nd[7];
    *(float4*)&u[((size_t)(b * M + m)) * 1024 + c * 4] = v;
}

// -------------------------------------------- grouped-conv GEMM + epilogue
template<int NROWS>
__device__ __forceinline__ void load_chunk_T(float dst[64][68],
                                             const float* __restrict__ base,
                                             int rstride, int vrows, int tid)
{
    constexpr int TPR = 256 / NROWS;
    int r = tid / TPR, f = tid % TPR;
    const float* rp = base + (size_t)r * (size_t)rstride;
    bool val = r < vrows;
    #pragma unroll
    for (int i = 0; i < 16 / TPR; i++) {
        int kq = (f + i * TPR) * 4;
        float4 t = val ? *(const float4*)(rp + kq) : make_float4(0.f,0.f,0.f,0.f);
        dst[kq+0][r]=t.x; dst[kq+1][r]=t.y; dst[kq+2][r]=t.z; dst[kq+3][r]=t.w;
    }
}

template<int PM>
__device__ __forceinline__ void mma_chunk(const float As[64][68], const float Bs[64][68],
                                          float acc[PM][4], int p0, int o0)
{
    #pragma unroll 16
    for (int k = 0; k < 64; k++) {
        float a[PM];
        #pragma unroll
        for (int i = 0; i < PM; i++) a[i] = As[k][p0 + i];
        float4 bv = *(const float4*)&Bs[k][o0];
        #pragma unroll
        for (int i = 0; i < PM; i++) {
            acc[i][0] = fmaf(a[i], bv.x, acc[i][0]);
            acc[i][1] = fmaf(a[i], bv.y, acc[i][1]);
            acc[i][2] = fmaf(a[i], bv.z, acc[i][2]);
            acc[i][3] = fmaf(a[i], bv.w, acc[i][3]);
        }
    }
}

template<int PM, int STAGE>
__global__ void __launch_bounds__(256) conv_gemm_kernel(
    const float* __restrict__ xsrc,
    const float* __restrict__ w_node, const float* __restrict__ b_node,
    const float* __restrict__ w_src,  const float* __restrict__ b_src,
    float* __restrict__ outp, float* __restrict__ score)
{
    constexpr int P  = PM * 16;
    constexpr int M  = (STAGE == 1) ? M1 : M2;
    constexpr int LS = (STAGE == 1) ? LEN1 : M1;
    const float* u   = (STAGE == 1) ? g_u1 : g_u2;
    const float* gtv = (STAGE == 1) ? g_gt1_0 : g_gt2;
    const float* xs  = (STAGE == 1) ? xsrc : g_out1;
    float*       out = (STAGE == 1) ? g_out1 : outp;

    __shared__ float As[64][68];
    __shared__ float Bs[64][68];
    __shared__ float s_red[16][P + 1];

    int tid = threadIdx.x;
    int og = tid & 15, pg = tid >> 4;
    int o0 = og * 4,  p0 = pg * PM;
    int b  = blockIdx.y;
    int m0 = blockIdx.x * P;
    int vrows = M - m0; if (vrows > P) vrows = P;

    float scp[PM];
    #pragma unroll
    for (int i = 0; i < PM; i++) scp[i] = 0.f;

    for (int g = 0; g < 4; g++) {
        float accS[PM][4], accN[PM][4];
        float4 bs4 = *(const float4*)&b_src[g * 64 + o0];
        float4 bn4 = *(const float4*)&b_node[g * 64 + o0];
        #pragma unroll
        for (int i = 0; i < PM; i++) {
            accS[i][0]=bs4.x; accS[i][1]=bs4.y; accS[i][2]=bs4.z; accS[i][3]=bs4.w;
            accN[i][0]=bn4.x; accN[i][1]=bn4.y; accN[i][2]=bn4.z; accN[i][3]=bn4.w;
        }
        __syncthreads();
        load_chunk_T<P >(As, xs + ((size_t)b * LS + m0) * CH + g * 64, CH, vrows, tid);
        load_chunk_T<64>(Bs, w_src + (size_t)g * 64 * 64, 64, 64, tid);
        __syncthreads();
        mma_chunk<PM>(As, Bs, accS, p0, o0);

        for (int kc = 0; kc < 4; kc++) {
            __syncthreads();
            load_chunk_T<P >(As, u + ((size_t)(b * M + m0)) * 1024 + g * 256 + kc * 64, 1024, vrows, tid);
            load_chunk_T<64>(Bs, w_node + (size_t)g * 64 * 256 + kc * 64, 256, 64, tid);
            __syncthreads();
            mma_chunk<PM>(As, Bs, accN, p0, o0);
        }

        #pragma unroll
        for (int i = 0; i < PM; i++) {
            int mg = m0 + p0 + i;
            if (mg < M) {
                float n0 = fmaxf(accN[i][0],0.f), n1 = fmaxf(accN[i][1],0.f);
                float n2 = fmaxf(accN[i][2],0.f), n3 = fmaxf(accN[i][3],0.f);
                float4 o4;
                o4.x = n0 + fmaxf(accS[i][0],0.f);
                o4.y = n1 + fmaxf(accS[i][1],0.f);
                o4.z = n2 + fmaxf(accS[i][2],0.f);
                o4.w = n3 + fmaxf(accS[i][3],0.f);
                *(float4*)&out[((size_t)b * M + mg) * CH + g * 64 + o0] = o4;

                if (STAGE == 2) {
                    const float* gp = &gtv[((size_t)b * M + mg) * CH + g * 64 + o0];
                    float d0 = gp[0]-n0, d1 = gp[1]-n1, d2 = gp[2]-n2, d3 = gp[3]-n3;
                    scp[i] += d0*d0 + d1*d1 + d2*d2 + d3*d3;
                } else if (m0 == 0 && (p0 + i) == 0) {
                    const float* gp = &gtv[b * CH + g * 64 + o0];
                    float d0 = gp[0]-n0, d1 = gp[1]-n1, d2 = gp[2]-n2, d3 = gp[3]-n3;
                    scp[i] += d0*d0 + d1*d1 + d2*d2 + d3*d3;
                }
            }
        }
    }

    #pragma unroll
    for (int i = 0; i < PM; i++) s_red[og][p0 + i] = scp[i];
    __syncthreads();
    if (STAGE == 2) {
        if (tid < P && m0 + tid < M) {
            float S = 0.f;
            #pragma unroll
            for (int w = 0; w < 16; w++) S += s_red[w][tid];
            score[(size_t)b * M + m0 + tid] = 1.f - expf(-0.5f * S);
        }
    } else {
        if (tid == 0 && m0 == 0) {
            float S = 0.f;
            #pragma unroll
            for (int w = 0; w < 16; w++) S += s_red[w][0];
            score[b] = 1.f - expf(-0.5f * S);
        }
    }
}

extern "C" void kernel_launch(void* const* d_in, const int* in_sizes, int n_in,
                              void* d_out, int out_size)
{
    const float* input  = (const float*)d_in[0];
    const float* gt     = (const float*)d_in[1];
    const float* w_att  = (const float*)d_in[2];
    const float* b_att  = (const float*)d_in[3];
    const float* w_gt1  = (const float*)d_in[4];
    const float* b_gt1  = (const float*)d_in[5];
    const float* w_gt2  = (const float*)d_in[6];
    const float* b_gt2  = (const float*)d_in[7];
    const float* w_agg1 = (const float*)d_in[8];
    const float* b_agg1 = (const float*)d_in[9];
    const float* w_src1 = (const float*)d_in[10];
    const float* b_src1 = (const float*)d_in[11];
    const float* w_agg2 = (const float*)d_in[12];
    const float* b_agg2 = (const float*)d_in[13];
    const float* w_src2 = (const float*)d_in[14];
    const float* b_src2 = (const float*)d_in[15];

    float* out    = (float*)d_out;                       // (B*512, 256)
    float* score1 = out + (size_t)NB * M2 * CH;          // (B,)
    float* score2 = score1 + NB;                         // (B*512,)

    gt_kernel<<<NB * M2 / 16, 256>>>(gt, w_gt1, b_gt1, w_gt2, b_gt2);
    aggregate_kernel<1><<<dim3(M1, NB), 256>>>(input, w_att, b_att);
    conv_gemm_kernel<4, 1><<<dim3((M1 + 63) / 64, NB), 256>>>(
        input, w_agg1, b_agg1, w_src1, b_src1, nullptr, score1);
    aggregate_kernel<2><<<dim3(M2, NB), 256>>>(input, w_att, b_att);
    conv_gemm_kernel<2, 2><<<dim3(M2 / 32, NB), 256>>>(
        input, w_agg2, b_agg2, w_src2, b_src2, out, score2);
}

// round 3
// speedup vs baseline: 1.0567x; 1.0567x over previous
#include <cuda_runtime.h>

#define NB   4
#define LEN1 32777
#define M1   4097
#define M2   512
#define CH   256

// ------- static scratch -------
__device__ float g_out1[NB * M1 * CH];
__device__ float g_gt2[NB * M2 * CH];
__device__ float g_gt1_0[NB * CH];
__device__ float g_attn[NB * M1 * 32];     // softmax attn, layout (b, m, n*4+h)
__device__ float g_rowdot[NB * LEN1 * 4];  // per-row dot with w_att, (b, r, h)

// ---- f32x2 helpers ----
__device__ __forceinline__ unsigned long long pk2(float v) {
    unsigned long long r; unsigned int u = __float_as_uint(v);
    asm("mov.b64 %0, {%1, %1};" : "=l"(r) : "r"(u));
    return r;
}
__device__ __forceinline__ void unpk2(unsigned long long v, float& lo, float& hi) {
    unsigned int a, b;
    asm("mov.b64 {%0, %1}, %2;" : "=r"(a), "=r"(b) : "l"(v));
    lo = __uint_as_float(a); hi = __uint_as_float(b);
}
#define FMA2(d, a, b) asm("fma.rn.f32x2 %0, %1, %2, %0;" : "+l"(d) : "l"(a), "l"(b))

// ------------------------------------------------ gt MLP (2 layers, relu)
__global__ void __launch_bounds__(256) gt_kernel(
    const float* __restrict__ gt,
    const float* __restrict__ w1, const float* __restrict__ b1,
    const float* __restrict__ w2, const float* __restrict__ b2)
{
    __shared__ float rs[16][256];
    __shared__ float g1[16][256];
    int tid = threadIdx.x, r0 = blockIdx.x * 16;
    #pragma unroll
    for (int i = 0; i < 16; i++) rs[i][tid] = gt[(size_t)(r0 + i) * CH + tid];
    __syncthreads();
    float acc[16];
    float bias = b1[tid];
    #pragma unroll
    for (int i = 0; i < 16; i++) acc[i] = bias;
    for (int c = 0; c < CH; c++) {
        float w = w1[c * CH + tid];
        #pragma unroll
        for (int i = 0; i < 16; i++) acc[i] = fmaf(rs[i][c], w, acc[i]);
    }
    #pragma unroll
    for (int i = 0; i < 16; i++) g1[i][tid] = fmaxf(acc[i], 0.f);
    __syncthreads();
    bias = b2[tid];
    #pragma unroll
    for (int i = 0; i < 16; i++) acc[i] = bias;
    for (int c = 0; c < CH; c++) {
        float w = w2[c * CH + tid];
        #pragma unroll
        for (int i = 0; i < 16; i++) acc[i] = fmaf(g1[i][c], w, acc[i]);
    }
    #pragma unroll
    for (int i = 0; i < 16; i++) {
        int r = r0 + i;
        g_gt2[(size_t)r * CH + tid] = fmaxf(acc[i], 0.f);
        if ((r & 511) == 0) g_gt1_0[(r >> 9) * CH + tid] = g1[i][tid];
    }
}

// ------------------------------------- per-row attention dots (streaming)
__global__ void __launch_bounds__(256) rowdot_kernel(
    const float* __restrict__ x, const float* __restrict__ w_att)
{
    __shared__ float wa_s[1024];
    int tid = threadIdx.x;
    *(float4*)&wa_s[tid * 4] = *(const float4*)&w_att[tid * 4];
    __syncthreads();
    int b = blockIdx.y;
    int r = blockIdx.x * 8 + (tid >> 5);
    if (r >= LEN1) return;
    int lane = tid & 31;
    const float* row = x + ((size_t)b * LEN1 + r) * CH;
    float s0 = 0.f, s1 = 0.f, s2 = 0.f, s3 = 0.f;
    #pragma unroll
    for (int j = 0; j < 8; j++) {
        int c = lane + 32 * j;
        float v = row[c];
        float4 w = *(const float4*)&wa_s[c * 4];
        s0 = fmaf(v, w.x, s0); s1 = fmaf(v, w.y, s1);
        s2 = fmaf(v, w.z, s2); s3 = fmaf(v, w.w, s3);
    }
    #pragma unroll
    for (int s = 16; s > 0; s >>= 1) {
        s0 += __shfl_xor_sync(0xffffffff, s0, s);
        s1 += __shfl_xor_sync(0xffffffff, s1, s);
        s2 += __shfl_xor_sync(0xffffffff, s2, s);
        s3 += __shfl_xor_sync(0xffffffff, s3, s);
    }
    if (lane < 4) {
        float v = (lane == 0) ? s0 : (lane == 1) ? s1 : (lane == 2) ? s2 : s3;
        g_rowdot[((size_t)b * LEN1 + r) * 4 + lane] = v;
    }
}

// ------------------------------------------------ softmax over 8 nodes
__global__ void __launch_bounds__(256) attn_softmax_kernel(const float* __restrict__ b_att)
{
    int tid = threadIdx.x, b = blockIdx.y;
    int m = blockIdx.x * 8 + (tid >> 5);
    if (m >= M1) return;
    int lane = tid & 31;
    int h = lane & 3;
    float lg = g_rowdot[((size_t)b * LEN1 + m) * 4 + h]
             + g_rowdot[((size_t)b * LEN1 + 8 * m + 1) * 4 + lane]
             + b_att[h];
    float mx = lg;
    #pragma unroll
    for (int msk = 4; msk <= 16; msk <<= 1)
        mx = fmaxf(mx, __shfl_xor_sync(0xffffffff, mx, msk));
    float e = expf(lg - mx);
    float sum = e;
    #pragma unroll
    for (int msk = 4; msk <= 16; msk <<= 1)
        sum += __shfl_xor_sync(0xffffffff, sum, msk);
    g_attn[((size_t)b * M1 + m) * 32 + lane] = e / sum;
}

// ------------------------------ fused aggregate + grouped-conv GEMM (f32x2)
template<int NROWS, int W>
__device__ __forceinline__ void load_T(float (*dst)[W], const float* __restrict__ base,
                                       int rstride, int vrows, int tid)
{
    constexpr int TPR = 256 / NROWS;
    int r = tid / TPR, f = tid % TPR;
    const float* rp = base + (size_t)r * rstride;
    bool val = r < vrows;
    #pragma unroll
    for (int i = 0; i < 16 / TPR; i++) {
        int kq = (f + i * TPR) * 4;
        float4 t = val ? *(const float4*)(rp + kq) : make_float4(0.f, 0.f, 0.f, 0.f);
        dst[kq + 0][r] = t.x; dst[kq + 1][r] = t.y;
        dst[kq + 2][r] = t.z; dst[kq + 3][r] = t.w;
    }
}

// As[k][p], k = c_local*4 + q-index, src K=64
template<int P>
__device__ __forceinline__ void build_src(float (*As)[P + 8], const float* __restrict__ xbase,
                                          int vrows, int tid)
{
    for (int it = tid; it < P * 16; it += 256) {
        int p = it % P, q = it / P;
        float4 v = (p < vrows) ? *(const float4*)(xbase + (size_t)p * CH + q * 4)
                               : make_float4(0.f, 0.f, 0.f, 0.f);
        As[q * 4 + 0][p] = v.x; As[q * 4 + 1][p] = v.y;
        As[q * 4 + 2][p] = v.z; As[q * 4 + 3][p] = v.w;
    }
}

// node chunk: As[(ci*4+t)][p] = attn[p][2t*4+g]*x[row(8p+2t)][ci] + attn[p][(2t+1)*4+g]*x[row(8p+2t+1)][ci]
template<int P>
__device__ __forceinline__ void build_node(float (*As)[P + 8], const float (*attn_s)[32],
                                           const float* __restrict__ xbase, int vrows,
                                           int g, int tid)
{
    for (int it = tid; it < P * 4; it += 256) {
        int p = it >> 2, t = it & 3;
        bool val = p < vrows;
        float a0 = val ? attn_s[p][(2 * t) * 4 + g] : 0.f;
        float a1 = val ? attn_s[p][(2 * t + 1) * 4 + g] : 0.f;
        const float* r0 = xbase + (size_t)(8 * p + 2 * t) * CH;
        const float* r1 = r0 + CH;
        #pragma unroll
        for (int q = 0; q < 4; q++) {
            float4 v0 = val ? *(const float4*)(r0 + q * 4) : make_float4(0.f, 0.f, 0.f, 0.f);
            float4 v1 = val ? *(const float4*)(r1 + q * 4) : make_float4(0.f, 0.f, 0.f, 0.f);
            As[(q * 4 + 0) * 4 + t][p] = a0 * v0.x + a1 * v1.x;
            As[(q * 4 + 1) * 4 + t][p] = a0 * v0.y + a1 * v1.y;
            As[(q * 4 + 2) * 4 + t][p] = a0 * v0.z + a1 * v1.z;
            As[(q * 4 + 3) * 4 + t][p] = a0 * v0.w + a1 * v1.w;
        }
    }
}

template<int P, int PPAIR>
__device__ __forceinline__ void mma_f2(const float (*As)[P + 8], const float (*Bs)[68],
                                       unsigned long long acc[PPAIR][4], int p0, int o0)
{
    #pragma unroll 4
    for (int k = 0; k < 64; k++) {
        unsigned long long a[PPAIR];
        #pragma unroll
        for (int j = 0; j < PPAIR; j++)
            a[j] = *(const unsigned long long*)&As[k][p0 + 2 * j];
        float4 bv = *(const float4*)&Bs[k][o0];
        unsigned long long B0 = pk2(bv.x), B1 = pk2(bv.y), B2 = pk2(bv.z), B3 = pk2(bv.w);
        #pragma unroll
        for (int j = 0; j < PPAIR; j++) {
            FMA2(acc[j][0], a[j], B0);
            FMA2(acc[j][1], a[j], B1);
            FMA2(acc[j][2], a[j], B2);
            FMA2(acc[j][3], a[j], B3);
        }
    }
}

template<int P, int STAGE>
__global__ void __launch_bounds__(256) conv_fused_kernel(
    const float* __restrict__ x_in,
    const float* __restrict__ w_node, const float* __restrict__ b_node,
    const float* __restrict__ w_src,  const float* __restrict__ b_src,
    float* __restrict__ outp, float* __restrict__ score)
{
    constexpr int PPAIR = P / 32;
    constexpr int PM    = 2 * PPAIR;
    constexpr int M     = (STAGE == 1) ? M1 : M2;
    constexpr int LS    = (STAGE == 1) ? LEN1 : M1;
    const float* x   = (STAGE == 1) ? x_in : g_out1;
    const float* gtv = (STAGE == 1) ? g_gt1_0 : g_gt2;
    float*       out = (STAGE == 1) ? g_out1 : outp;

    __shared__ float As[64][P + 8];
    __shared__ float Bs[64][68];
    __shared__ float attn_s[P][32];
    __shared__ float s_red[16][P];

    int tid = threadIdx.x;
    int og = tid & 15, pg = tid >> 4;
    int o0 = og * 4,  p0 = pg * PM;
    int b  = blockIdx.y;
    int m0 = blockIdx.x * P;
    int vrows = M - m0; if (vrows > P) vrows = P;

    // attention tile
    for (int i = tid; i < P * 32; i += 256) {
        int p = i >> 5;
        attn_s[p][i & 31] = (p < vrows)
            ? g_attn[((size_t)b * M1 + m0 + p) * 32 + (i & 31)] : 0.f;
    }

    float scp[PM];
    #pragma unroll
    for (int i = 0; i < PM; i++) scp[i] = 0.f;

    const float* node_base = x + ((size_t)b * LS + 8 * (size_t)m0 + 1) * CH;
    const float* src_base  = x + ((size_t)b * LS + m0) * CH;

    for (int g = 0; g < 4; g++) {
        unsigned long long accS[PPAIR][4], accN[PPAIR][4];
        float4 bs4 = *(const float4*)&b_src[g * 64 + o0];
        float4 bn4 = *(const float4*)&b_node[g * 64 + o0];
        #pragma unroll
        for (int j = 0; j < PPAIR; j++) {
            accS[j][0] = pk2(bs4.x); accS[j][1] = pk2(bs4.y);
            accS[j][2] = pk2(bs4.z); accS[j][3] = pk2(bs4.w);
            accN[j][0] = pk2(bn4.x); accN[j][1] = pk2(bn4.y);
            accN[j][2] = pk2(bn4.z); accN[j][3] = pk2(bn4.w);
        }

        // src conv (K=64)
        __syncthreads();
        build_src<P>(As, src_base + g * 64, vrows, tid);
        load_T<64, 68>(Bs, w_src + (size_t)g * 64 * 64, 64, 64, tid);
        __syncthreads();
        mma_f2<P, PPAIR>(As, Bs, accS, p0, o0);

        // node conv (K=256, 4 chunks) — aggregation fused into As build
        for (int kc = 0; kc < 4; kc++) {
            __syncthreads();
            build_node<P>(As, attn_s, node_base + g * 64 + kc * 16, vrows, g, tid);
            load_T<64, 68>(Bs, w_node + (size_t)g * 64 * 256 + kc * 64, 256, 64, tid);
            __syncthreads();
            mma_f2<P, PPAIR>(As, Bs, accN, p0, o0);
        }

        // epilogue for this group
        #pragma unroll
        for (int j = 0; j < PPAIR; j++) {
            float nlo[4], nhi[4], slo[4], shi[4];
            #pragma unroll
            for (int o = 0; o < 4; o++) {
                unpk2(accN[j][o], nlo[o], nhi[o]);
                unpk2(accS[j][o], slo[o], shi[o]);
            }
            #pragma unroll
            for (int lh = 0; lh < 2; lh++) {
                int pos = p0 + 2 * j + lh;
                int mg  = m0 + pos;
                if (mg < M) {
                    float n0 = fmaxf(lh ? nhi[0] : nlo[0], 0.f);
                    float n1 = fmaxf(lh ? nhi[1] : nlo[1], 0.f);
                    float n2 = fmaxf(lh ? nhi[2] : nlo[2], 0.f);
                    float n3 = fmaxf(lh ? nhi[3] : nlo[3], 0.f);
                    float4 o4;
                    o4.x = n0 + fmaxf(lh ? shi[0] : slo[0], 0.f);
                    o4.y = n1 + fmaxf(lh ? shi[1] : slo[1], 0.f);
                    o4.z = n2 + fmaxf(lh ? shi[2] : slo[2], 0.f);
                    o4.w = n3 + fmaxf(lh ? shi[3] : slo[3], 0.f);
                    *(float4*)&out[((size_t)b * M + mg) * CH + g * 64 + o0] = o4;

                    if (STAGE == 2) {
                        const float* gp = &gtv[((size_t)b * M + mg) * CH + g * 64 + o0];
                        float d0 = gp[0] - n0, d1 = gp[1] - n1;
                        float d2 = gp[2] - n2, d3 = gp[3] - n3;
                        scp[2 * j + lh] += d0 * d0 + d1 * d1 + d2 * d2 + d3 * d3;
                    } else if (mg == 0) {
                        const float* gp = &gtv[b * CH + g * 64 + o0];
                        float d0 = gp[0] - n0, d1 = gp[1] - n1;
                        float d2 = gp[2] - n2, d3 = gp[3] - n3;
                        scp[2 * j + lh] += d0 * d0 + d1 * d1 + d2 * d2 + d3 * d3;
                    }
                }
            }
        }
    }

    __syncthreads();
    #pragma unroll
    for (int i = 0; i < PM; i++) s_red[og][p0 + i] = scp[i];
    __syncthreads();
    if (STAGE == 2) {
        if (tid < P && m0 + tid < M) {
            float S = 0.f;
            #pragma unroll
            for (int w = 0; w < 16; w++) S += s_red[w][tid];
            score[(size_t)b * M + m0 + tid] = 1.f - expf(-0.5f * S);
        }
    } else {
        if (tid == 0 && m0 == 0) {
            float S = 0.f;
            #pragma unroll
            for (int w = 0; w < 16; w++) S += s_red[w][0];
            score[b] = 1.f - expf(-0.5f * S);
        }
    }
}

extern "C" void kernel_launch(void* const* d_in, const int* in_sizes, int n_in,
                              void* d_out, int out_size)
{
    const float* input  = (const float*)d_in[0];
    const float* gt     = (const float*)d_in[1];
    const float* w_att  = (const float*)d_in[2];
    const float* b_att  = (const float*)d_in[3];
    const float* w_gt1  = (const float*)d_in[4];
    const float* b_gt1  = (const float*)d_in[5];
    const float* w_gt2  = (const float*)d_in[6];
    const float* b_gt2  = (const float*)d_in[7];
    const float* w_agg1 = (const float*)d_in[8];
    const float* b_agg1 = (const float*)d_in[9];
    const float* w_src1 = (const float*)d_in[10];
    const float* b_src1 = (const float*)d_in[11];
    const float* w_agg2 = (const float*)d_in[12];
    const float* b_agg2 = (const float*)d_in[13];
    const float* w_src2 = (const float*)d_in[14];
    const float* b_src2 = (const float*)d_in[15];

    float* out    = (float*)d_out;                 // (B*512, 256)
    float* score1 = out + (size_t)NB * M2 * CH;    // (B,)
    float* score2 = score1 + NB;                   // (B*512,)

    gt_kernel<<<NB * M2 / 16, 256>>>(gt, w_gt1, b_gt1, w_gt2, b_gt2);
    rowdot_kernel<<<dim3((LEN1 + 7) / 8, NB), 256>>>(input, w_att);
    attn_softmax_kernel<<<dim3((M1 + 7) / 8, NB), 256>>>(b_att);
    conv_fused_kernel<64, 1><<<dim3((M1 + 63) / 64, NB), 256>>>(
        input, w_agg1, b_agg1, w_src1, b_src1, nullptr, score1);
    conv_fused_kernel<32, 2><<<dim3(M2 / 32, NB), 256>>>(
        input, w_agg2, b_agg2, w_src2, b_src2, out, score2);
}

// round 4
// speedup vs baseline: 1.5192x; 1.4377x over previous
#include <cuda_runtime.h>

#define NB   4
#define LEN1 32777
#define M1   4097
#define M2   512
#define CH   256

typedef unsigned long long u64;

// ------- static scratch -------
__device__ float g_out1[NB * M1 * CH];
__device__ float g_gt2[NB * M2 * CH];
__device__ float g_gt1_0[NB * CH];
__device__ float g_attn[NB * M1 * 32];     // softmax attn, (b, m, n*4+h)
__device__ float g_rowdot[NB * LEN1 * 4];  // per-row dot with w_att
__device__ float g_sc1[NB];
__device__ float g_sc2[NB * M2];

// ---- f32x2 helpers ----
__device__ __forceinline__ u64 pk2(float v) {
    u64 r; unsigned int u = __float_as_uint(v);
    asm("mov.b64 %0, {%1, %1};" : "=l"(r) : "r"(u));
    return r;
}
__device__ __forceinline__ void unpk2(u64 v, float& lo, float& hi) {
    unsigned int a, b;
    asm("mov.b64 {%0, %1}, %2;" : "=r"(a), "=r"(b) : "l"(v));
    lo = __uint_as_float(a); hi = __uint_as_float(b);
}
#define FMA2(d, a, b) asm("fma.rn.f32x2 %0, %1, %2, %0;" : "+l"(d) : "l"(a), "l"(b))

// --------------------------------------------------------- init / finalize
__global__ void init_kernel() {
    int i = blockIdx.x * 256 + threadIdx.x;
    if (i < NB) g_sc1[i] = 0.f;
    if (i < NB * M2) g_sc2[i] = 0.f;
}
__global__ void finalize_kernel(float* score1, float* score2) {
    int i = blockIdx.x * 256 + threadIdx.x;
    if (i < NB) score1[i] = 1.f - expf(-0.5f * g_sc1[i]);
    if (i < NB * M2) score2[i] = 1.f - expf(-0.5f * g_sc2[i]);
}

// ------------------------------------------------ gt MLP (f32x2, row pairs)
__global__ void __launch_bounds__(256) gt_kernel(
    const float* __restrict__ gt,
    const float* __restrict__ w1, const float* __restrict__ b1,
    const float* __restrict__ w2, const float* __restrict__ b2)
{
    __shared__ float rsT[256][20];   // [channel][row] transposed, pad 20 (16B-aligned rows)
    __shared__ float g1T[256][20];
    int tid = threadIdx.x, r0 = blockIdx.x * 16;

    #pragma unroll
    for (int i = 0; i < 16; i++)
        rsT[tid][i] = gt[(size_t)(r0 + i) * CH + tid];
    __syncthreads();

    u64 acc[8];
    {
        u64 bb = pk2(b1[tid]);
        #pragma unroll
        for (int j = 0; j < 8; j++) acc[j] = bb;
        for (int c = 0; c < CH; c++) {
            u64 w = pk2(w1[c * CH + tid]);
            const ulonglong2* rp = (const ulonglong2*)&rsT[c][0];
            #pragma unroll
            for (int q = 0; q < 4; q++) {
                ulonglong2 a2 = rp[q];
                FMA2(acc[2 * q + 0], a2.x, w);
                FMA2(acc[2 * q + 1], a2.y, w);
            }
        }
    }
    #pragma unroll
    for (int j = 0; j < 8; j++) {
        float lo, hi; unpk2(acc[j], lo, hi);
        g1T[tid][2 * j]     = fmaxf(lo, 0.f);
        g1T[tid][2 * j + 1] = fmaxf(hi, 0.f);
    }
    if ((r0 & 511) == 0) g_gt1_0[(r0 >> 9) * CH + tid] = fmaxf(__uint_as_float((unsigned int)acc[0]), 0.f) ;
    __syncthreads();

    {
        u64 bb = pk2(b2[tid]);
        #pragma unroll
        for (int j = 0; j < 8; j++) acc[j] = bb;
        for (int c = 0; c < CH; c++) {
            u64 w = pk2(w2[c * CH + tid]);
            const ulonglong2* rp = (const ulonglong2*)&g1T[c][0];
            #pragma unroll
            for (int q = 0; q < 4; q++) {
                ulonglong2 a2 = rp[q];
                FMA2(acc[2 * q + 0], a2.x, w);
                FMA2(acc[2 * q + 1], a2.y, w);
            }
        }
    }
    #pragma unroll
    for (int j = 0; j < 8; j++) {
        float lo, hi; unpk2(acc[j], lo, hi);
        g_gt2[(size_t)(r0 + 2 * j)     * CH + tid] = fmaxf(lo, 0.f);
        g_gt2[(size_t)(r0 + 2 * j + 1) * CH + tid] = fmaxf(hi, 0.f);
    }
}

// ------------------------------------- per-row attention dots (streaming)
__global__ void __launch_bounds__(256) rowdot_kernel(
    const float* __restrict__ x, const float* __restrict__ w_att)
{
    __shared__ float wa_s[1024];
    int tid = threadIdx.x;
    *(float4*)&wa_s[tid * 4] = *(const float4*)&w_att[tid * 4];
    __syncthreads();
    int b = blockIdx.y;
    int r = blockIdx.x * 8 + (tid >> 5);
    if (r >= LEN1) return;
    int lane = tid & 31;
    const float* row = x + ((size_t)b * LEN1 + r) * CH;
    float s0 = 0.f, s1 = 0.f, s2 = 0.f, s3 = 0.f;
    #pragma unroll
    for (int j = 0; j < 8; j++) {
        int c = lane + 32 * j;
        float v = row[c];
        float4 w = *(const float4*)&wa_s[c * 4];
        s0 = fmaf(v, w.x, s0); s1 = fmaf(v, w.y, s1);
        s2 = fmaf(v, w.z, s2); s3 = fmaf(v, w.w, s3);
    }
    #pragma unroll
    for (int s = 16; s > 0; s >>= 1) {
        s0 += __shfl_xor_sync(0xffffffff, s0, s);
        s1 += __shfl_xor_sync(0xffffffff, s1, s);
        s2 += __shfl_xor_sync(0xffffffff, s2, s);
        s3 += __shfl_xor_sync(0xffffffff, s3, s);
    }
    if (lane < 4) {
        float v = (lane == 0) ? s0 : (lane == 1) ? s1 : (lane == 2) ? s2 : s3;
        g_rowdot[((size_t)b * LEN1 + r) * 4 + lane] = v;
    }
}

// ------------------------------------------------ softmax over 8 nodes
__global__ void __launch_bounds__(256) attn_softmax_kernel(const float* __restrict__ b_att)
{
    int tid = threadIdx.x, b = blockIdx.y;
    int m = blockIdx.x * 8 + (tid >> 5);
    if (m >= M1) return;
    int lane = tid & 31;
    int h = lane & 3;
    float lg = g_rowdot[((size_t)b * LEN1 + m) * 4 + h]
             + g_rowdot[((size_t)b * LEN1 + 8 * m + 1) * 4 + lane]
             + b_att[h];
    float mx = lg;
    #pragma unroll
    for (int msk = 4; msk <= 16; msk <<= 1)
        mx = fmaxf(mx, __shfl_xor_sync(0xffffffff, mx, msk));
    float e = expf(lg - mx);
    float sum = e;
    #pragma unroll
    for (int msk = 4; msk <= 16; msk <<= 1)
        sum += __shfl_xor_sync(0xffffffff, sum, msk);
    g_attn[((size_t)b * M1 + m) * 32 + lane] = e / sum;
}

// ----------------------------- fused conv (one group per block, f32x2 GEMM)
template<int P>
__device__ __forceinline__ void load_w(float (*Bs)[68], const float* __restrict__ base,
                                       int rstride, int tid)
{
    int r = tid >> 2, f = tid & 3;            // 64 rows (outputs), 4 threads/row
    const float* rp = base + (size_t)r * rstride;
    #pragma unroll
    for (int i = 0; i < 4; i++) {
        int kq = (f + i * 4) * 4;
        float4 t = *(const float4*)(rp + kq);
        Bs[kq + 0][r] = t.x; Bs[kq + 1][r] = t.y;
        Bs[kq + 2][r] = t.z; Bs[kq + 3][r] = t.w;
    }
}

template<int P>
__device__ __forceinline__ void mma_block(const float (*As)[P + 8], const float (*Bs)[68],
                                          u64 acc[4][4], int p0, int o0)
{
    #pragma unroll 8
    for (int k = 0; k < 64; k++) {
        float4 av = *(const float4*)&As[k][p0];
        ulonglong2 w0 = *(const ulonglong2*)&Bs[k][o0];
        ulonglong2 w1 = *(const ulonglong2*)&Bs[k][o0 + 32];
        u64 ap0 = pk2(av.x), ap1 = pk2(av.y), ap2 = pk2(av.z), ap3 = pk2(av.w);
        FMA2(acc[0][0], w0.x, ap0); FMA2(acc[0][1], w0.y, ap0);
        FMA2(acc[0][2], w1.x, ap0); FMA2(acc[0][3], w1.y, ap0);
        FMA2(acc[1][0], w0.x, ap1); FMA2(acc[1][1], w0.y, ap1);
        FMA2(acc[1][2], w1.x, ap1); FMA2(acc[1][3], w1.y, ap1);
        FMA2(acc[2][0], w0.x, ap2); FMA2(acc[2][1], w0.y, ap2);
        FMA2(acc[2][2], w1.x, ap2); FMA2(acc[2][3], w1.y, ap2);
        FMA2(acc[3][0], w0.x, ap3); FMA2(acc[3][1], w0.y, ap3);
        FMA2(acc[3][2], w1.x, ap3); FMA2(acc[3][3], w1.y, ap3);
    }
}

template<int P, int STAGE>
__global__ void __launch_bounds__(256, 2) conv_fused_kernel(
    const float* __restrict__ x_in,
    const float* __restrict__ w_node, const float* __restrict__ b_node,
    const float* __restrict__ w_src,  const float* __restrict__ b_src,
    float* __restrict__ outp)
{
    constexpr int M  = (STAGE == 1) ? M1 : M2;
    constexpr int LS = (STAGE == 1) ? LEN1 : M1;
    const float* x   = (STAGE == 1) ? x_in : g_out1;
    const float* gtv = (STAGE == 1) ? g_gt1_0 : g_gt2;
    float*       out = (STAGE == 1) ? g_out1 : outp;

    extern __shared__ float smem[];
    float (*As)[P + 8]   = (float(*)[P + 8])smem;
    float (*Bs)[68]      = (float(*)[68])(smem + 64 * (P + 8));
    float (*attn_s)[8]   = (float(*)[8])(smem + 64 * (P + 8) + 64 * 68);
    float (*s_red)[8]    = (float(*)[8])(smem + 64 * (P + 8) + 64 * 68 + P * 8);

    int tid = threadIdx.x;
    int og = tid & 7, pg = tid >> 3;
    int o0 = og * 4;               // outputs {o0..o0+3, o0+32..o0+35}
    int p0 = pg * 4;
    int b  = blockIdx.y, g = blockIdx.z;
    int m0 = blockIdx.x * P;
    int vrows = M - m0; if (vrows > P) vrows = P;
    int c0 = g * 64;

    for (int i = tid; i < P * 8; i += 256) {
        int p = i >> 3, n = i & 7;
        attn_s[p][n] = (p < vrows)
            ? g_attn[((size_t)b * M1 + m0 + p) * 32 + n * 4 + g] : 0.f;
    }

    const float* node_base = x + ((size_t)b * LS + 8 * (size_t)m0 + 1) * CH + c0;
    const float* src_base  = x + ((size_t)b * LS + m0) * CH + c0;

    u64 accN[4][4], accS[4][4];
    {
        ulonglong2 bn0 = *(const ulonglong2*)&b_node[c0 + o0];
        ulonglong2 bn1 = *(const ulonglong2*)&b_node[c0 + o0 + 32];
        ulonglong2 bs0 = *(const ulonglong2*)&b_src[c0 + o0];
        ulonglong2 bs1 = *(const ulonglong2*)&b_src[c0 + o0 + 32];
        #pragma unroll
        for (int p = 0; p < 4; p++) {
            accN[p][0] = bn0.x; accN[p][1] = bn0.y; accN[p][2] = bn1.x; accN[p][3] = bn1.y;
            accS[p][0] = bs0.x; accS[p][1] = bs0.y; accS[p][2] = bs1.x; accS[p][3] = bs1.y;
        }
    }

    // node conv: K = 256 (ci*4 + t), 4 chunks of 64
    for (int kc = 0; kc < 4; kc++) {
        __syncthreads();
        for (int it = tid; it < P * 4; it += 256) {
            int p = it >> 2, t = it & 3;
            bool val = p < vrows;
            float a0 = val ? attn_s[p][2 * t]     : 0.f;
            float a1 = val ? attn_s[p][2 * t + 1] : 0.f;
            const float* r0p = node_base + (size_t)(8 * p + 2 * t) * CH + kc * 16;
            const float* r1p = r0p + CH;
            #pragma unroll
            for (int q = 0; q < 4; q++) {
                float4 v0 = val ? *(const float4*)(r0p + q * 4) : make_float4(0.f,0.f,0.f,0.f);
                float4 v1 = val ? *(const float4*)(r1p + q * 4) : make_float4(0.f,0.f,0.f,0.f);
                As[(q * 4 + 0) * 4 + t][p] = a0 * v0.x + a1 * v1.x;
                As[(q * 4 + 1) * 4 + t][p] = a0 * v0.y + a1 * v1.y;
                As[(q * 4 + 2) * 4 + t][p] = a0 * v0.z + a1 * v1.z;
                As[(q * 4 + 3) * 4 + t][p] = a0 * v0.w + a1 * v1.w;
            }
        }
        load_w<P>(Bs, w_node + (size_t)c0 * 256 + kc * 64, 256, tid);
        __syncthreads();
        mma_block<P>(As, Bs, accN, p0, o0);
    }

    // src conv: K = 64
    __syncthreads();
    for (int it = tid; it < P * 16; it += 256) {
        int p = it % P, q = it / P;
        float4 v = (p < vrows) ? *(const float4*)(src_base + (size_t)p * CH + q * 4)
                               : make_float4(0.f, 0.f, 0.f, 0.f);
        As[q * 4 + 0][p] = v.x; As[q * 4 + 1][p] = v.y;
        As[q * 4 + 2][p] = v.z; As[q * 4 + 3][p] = v.w;
    }
    load_w<P>(Bs, w_src + (size_t)c0 * 64, 64, tid);
    __syncthreads();
    mma_block<P>(As, Bs, accS, p0, o0);

    // epilogue
    #pragma unroll
    for (int pi = 0; pi < 4; pi++) {
        int mg = m0 + p0 + pi;
        float n[8], s[8];
        unpk2(accN[pi][0], n[0], n[1]); unpk2(accN[pi][1], n[2], n[3]);
        unpk2(accN[pi][2], n[4], n[5]); unpk2(accN[pi][3], n[6], n[7]);
        unpk2(accS[pi][0], s[0], s[1]); unpk2(accS[pi][1], s[2], s[3]);
        unpk2(accS[pi][2], s[4], s[5]); unpk2(accS[pi][3], s[6], s[7]);
        #pragma unroll
        for (int o = 0; o < 8; o++) { n[o] = fmaxf(n[o], 0.f); s[o] = fmaxf(s[o], 0.f); }
        if (mg < M) {
            float* op = &out[((size_t)b * M + mg) * CH + c0];
            *(float4*)(op + o0)      = make_float4(n[0]+s[0], n[1]+s[1], n[2]+s[2], n[3]+s[3]);
            *(float4*)(op + o0 + 32) = make_float4(n[4]+s[4], n[5]+s[5], n[6]+s[6], n[7]+s[7]);
            if (STAGE == 2) {
                const float* gp = &gtv[((size_t)b * M + mg) * CH + c0];
                float4 g0 = *(const float4*)(gp + o0);
                float4 g1 = *(const float4*)(gp + o0 + 32);
                float d;
                float S = 0.f;
                d = g0.x - n[0]; S += d*d;  d = g0.y - n[1]; S += d*d;
                d = g0.z - n[2]; S += d*d;  d = g0.w - n[3]; S += d*d;
                d = g1.x - n[4]; S += d*d;  d = g1.y - n[5]; S += d*d;
                d = g1.z - n[6]; S += d*d;  d = g1.w - n[7]; S += d*d;
                s_red[p0 + pi][og] = S;
            } else if (mg == 0) {
                const float* gp = &gtv[b * CH + c0];
                float4 g0 = *(const float4*)(gp + o0);
                float4 g1 = *(const float4*)(gp + o0 + 32);
                float d;
                float S = 0.f;
                d = g0.x - n[0]; S += d*d;  d = g0.y - n[1]; S += d*d;
                d = g0.z - n[2]; S += d*d;  d = g0.w - n[3]; S += d*d;
                d = g1.x - n[4]; S += d*d;  d = g1.y - n[5]; S += d*d;
                d = g1.z - n[6]; S += d*d;  d = g1.w - n[7]; S += d*d;
                atomicAdd(&g_sc1[b], S);
            }
        }
    }
    if (STAGE == 2) {
        __syncthreads();
        if (tid < P) {
            float S = 0.f;
            #pragma unroll
            for (int o = 0; o < 8; o++) S += s_red[tid][o];
            atomicAdd(&g_sc2[(size_t)b * M2 + m0 + tid], S);
        }
    }
}

extern "C" void kernel_launch(void* const* d_in, const int* in_sizes, int n_in,
                              void* d_out, int out_size)
{
    const float* input  = (const float*)d_in[0];
    const float* gt     = (const float*)d_in[1];
    const float* w_att  = (const float*)d_in[2];
    const float* b_att  = (const float*)d_in[3];
    const float* w_gt1  = (const float*)d_in[4];
    const float* b_gt1  = (const float*)d_in[5];
    const float* w_gt2  = (const float*)d_in[6];
    const float* b_gt2  = (const float*)d_in[7];
    const float* w_agg1 = (const float*)d_in[8];
    const float* b_agg1 = (const float*)d_in[9];
    const float* w_src1 = (const float*)d_in[10];
    const float* b_src1 = (const float*)d_in[11];
    const float* w_agg2 = (const float*)d_in[12];
    const float* b_agg2 = (const float*)d_in[13];
    const float* w_src2 = (const float*)d_in[14];
    const float* b_src2 = (const float*)d_in[15];

    float* out    = (float*)d_out;                 // (B*512, 256)
    float* score1 = out + (size_t)NB * M2 * CH;    // (B,)
    float* score2 = score1 + NB;                   // (B*512,)

    constexpr int SMEM_CONV = (64 * 136 + 64 * 68 + 128 * 8 * 2) * 4;
    static bool attr_set = false;
    if (!attr_set) {
        cudaFuncSetAttribute(conv_fused_kernel<128, 1>,
                             cudaFuncAttributeMaxDynamicSharedMemorySize, SMEM_CONV);
        cudaFuncSetAttribute(conv_fused_kernel<128, 2>,
                             cudaFuncAttributeMaxDynamicSharedMemorySize, SMEM_CONV);
        attr_set = true;
    }

    init_kernel<<<(NB * M2 + 255) / 256, 256>>>();
    gt_kernel<<<NB * M2 / 16, 256>>>(gt, w_gt1, b_gt1, w_gt2, b_gt2);
    rowdot_kernel<<<dim3((LEN1 + 7) / 8, NB), 256>>>(input, w_att);
    attn_softmax_kernel<<<dim3((M1 + 7) / 8, NB), 256>>>(b_att);
    conv_fused_kernel<128, 1><<<dim3((M1 + 127) / 128, NB, 4), 256, SMEM_CONV>>>(
        input, w_agg1, b_agg1, w_src1, b_src1, nullptr);
    conv_fused_kernel<128, 2><<<dim3(M2 / 128, NB, 4), 256, SMEM_CONV>>>(
        input, w_agg2, b_agg2, w_src2, b_src2, out);
    finalize_kernel<<<(NB * M2 + 255) / 256, 256>>>(score1, score2);
}